// round 2
// baseline (speedup 1.0000x reference)
#include <cuda_runtime.h>
#include <cstdint>

// Problem constants (match reference)
#define NV   100000
#define NE   20000
#define DD   64
#define ALPHA 0.5f
#define BETA  0.5f

// Scratch: edge accumulator and vertex accumulator (16B aligned for red.v4)
__device__ __align__(16) float g_Xe[NE * DD];
__device__ __align__(16) float g_Xv[NV * DD];

// ---------------------------------------------------------------------------
// Zero both scratch buffers (float4 stores, grid-stride)
// ---------------------------------------------------------------------------
__global__ void zero_scratch() {
    const size_t n4e = (size_t)NE * DD / 4;
    const size_t n4v = (size_t)NV * DD / 4;
    const size_t n4  = n4e + n4v;
    float4 z = make_float4(0.f, 0.f, 0.f, 0.f);
    size_t stride = (size_t)gridDim.x * blockDim.x;
    for (size_t i = (size_t)blockIdx.x * blockDim.x + threadIdx.x; i < n4; i += stride) {
        if (i < n4e) reinterpret_cast<float4*>(g_Xe)[i] = z;
        else         reinterpret_cast<float4*>(g_Xv)[i - n4e] = z;
    }
}

// ---------------------------------------------------------------------------
// red.global.add.v4.f32 wrapper (sm_90+ vector reduction, 16B granularity)
// ---------------------------------------------------------------------------
__device__ __forceinline__ void red_add_v4(float* dst, float4 v) {
    asm volatile("red.global.add.v4.f32 [%0], {%1, %2, %3, %4};"
                 :: "l"(dst), "f"(v.x), "f"(v.y), "f"(v.z), "f"(v.w)
                 : "memory");
}

// ---------------------------------------------------------------------------
// Phase 1: Xe[e] += X[v]  — 16 threads per nnz entry, float4 each
// ---------------------------------------------------------------------------
__global__ void scatter_v2e(const float* __restrict__ X,
                            const int* __restrict__ vertex,
                            const int* __restrict__ edges,
                            int nnz) {
    int t = blockIdx.x * blockDim.x + threadIdx.x;
    int i = t >> 4;
    if (i >= nnz) return;
    int c = (t & 15) << 2;                 // float offset within row, 16B aligned
    int v = __ldg(vertex + i);
    int e = __ldg(edges + i);
    float4 val = *reinterpret_cast<const float4*>(X + (size_t)v * DD + c);
    red_add_v4(g_Xe + (size_t)e * DD + c, val);
}

// ---------------------------------------------------------------------------
// Phase 2: Xv[v] += Xe[e]
// ---------------------------------------------------------------------------
__global__ void scatter_e2v(const int* __restrict__ vertex,
                            const int* __restrict__ edges,
                            int nnz) {
    int t = blockIdx.x * blockDim.x + threadIdx.x;
    int i = t >> 4;
    if (i >= nnz) return;
    int c = (t & 15) << 2;
    int v = __ldg(vertex + i);
    int e = __ldg(edges + i);
    float4 val = *reinterpret_cast<const float4*>(g_Xe + (size_t)e * DD + c);
    red_add_v4(g_Xv + (size_t)v * DD + c, val);
}

// ---------------------------------------------------------------------------
// Epilogue: Xi = 0.5*Xv + 0.5*X0 ; h = relu(Xi@W1 + b1) ;
//           out = 0.5*Xi + 0.5*(h@W2 + b2)
// One block = 64 rows. 256 threads, each computes a 4x4 output block.
// Smem: S[64][65] holds Xi then h (padded: bank-conflict-free column reads),
//       Ws[64][64] holds W1 then W2.
// ---------------------------------------------------------------------------
__global__ __launch_bounds__(256) void epilogue(
        const float* __restrict__ X0,
        const float* __restrict__ W1, const float* __restrict__ b1,
        const float* __restrict__ W2, const float* __restrict__ b2,
        float* __restrict__ out) {
    __shared__ float S[64 * 65];
    __shared__ float Ws[64 * 64];
    __shared__ float bs[64];

    const int tid  = threadIdx.x;
    const int tr   = tid >> 4;          // 0..15 row-group
    const int tc   = tid & 15;          // 0..15 col-group
    const int r0   = tr * 4;
    const int c0   = tc * 4;
    const int base = blockIdx.x * 64;

    // Load W1 + b1
    #pragma unroll
    for (int idx = tid; idx < 64 * 16; idx += 256)
        reinterpret_cast<float4*>(Ws)[idx] = reinterpret_cast<const float4*>(W1)[idx];
    if (tid < 64) bs[tid] = b1[tid];

    // Load Xi tile (fused 0.5*Xv + 0.5*X0), row-major into padded smem
    for (int idx = tid; idx < 64 * 16; idx += 256) {
        int r = idx >> 4;
        int q = (idx & 15) << 2;
        int row = base + r;
        float4 xv = make_float4(0.f, 0.f, 0.f, 0.f);
        float4 x0 = xv;
        if (row < NV) {
            xv = *reinterpret_cast<const float4*>(g_Xv + (size_t)row * DD + q);
            x0 = *reinterpret_cast<const float4*>(X0   + (size_t)row * DD + q);
        }
        float* s = S + r * 65 + q;
        s[0] = (1.f - ALPHA) * xv.x + ALPHA * x0.x;
        s[1] = (1.f - ALPHA) * xv.y + ALPHA * x0.y;
        s[2] = (1.f - ALPHA) * xv.z + ALPHA * x0.z;
        s[3] = (1.f - ALPHA) * xv.w + ALPHA * x0.w;
    }
    __syncthreads();

    // GEMM 1: acc = Xi @ W1
    float acc[4][4] = {};
    #pragma unroll 16
    for (int k = 0; k < 64; ++k) {
        float a[4];
        #pragma unroll
        for (int i = 0; i < 4; ++i) a[i] = S[(r0 + i) * 65 + k];
        float4 b = *reinterpret_cast<const float4*>(Ws + k * 64 + c0);
        #pragma unroll
        for (int i = 0; i < 4; ++i) {
            acc[i][0] = fmaf(a[i], b.x, acc[i][0]);
            acc[i][1] = fmaf(a[i], b.y, acc[i][1]);
            acc[i][2] = fmaf(a[i], b.z, acc[i][2]);
            acc[i][3] = fmaf(a[i], b.w, acc[i][3]);
        }
    }

    // Stash this thread's Xi 4x4 block for the residual before S is reused
    float xi[4][4];
    #pragma unroll
    for (int i = 0; i < 4; ++i)
        #pragma unroll
        for (int j = 0; j < 4; ++j)
            xi[i][j] = S[(r0 + i) * 65 + c0 + j];
    __syncthreads();   // all reads of S / Ws done

    // Write h = relu(acc + b1) into S; load W2 + b2 into Ws
    #pragma unroll
    for (int i = 0; i < 4; ++i)
        #pragma unroll
        for (int j = 0; j < 4; ++j)
            S[(r0 + i) * 65 + c0 + j] = fmaxf(acc[i][j] + bs[c0 + j], 0.f);

    #pragma unroll
    for (int idx = tid; idx < 64 * 16; idx += 256)
        reinterpret_cast<float4*>(Ws)[idx] = reinterpret_cast<const float4*>(W2)[idx];
    __syncthreads();   // h + W2 ready (bs overwritten after this sync is unsafe -> do b2 via reg)

    float b2r[4];
    #pragma unroll
    for (int j = 0; j < 4; ++j) b2r[j] = __ldg(b2 + c0 + j);

    // GEMM 2: acc = h @ W2
    #pragma unroll
    for (int i = 0; i < 4; ++i)
        #pragma unroll
        for (int j = 0; j < 4; ++j)
            acc[i][j] = 0.f;
    #pragma unroll 16
    for (int k = 0; k < 64; ++k) {
        float a[4];
        #pragma unroll
        for (int i = 0; i < 4; ++i) a[i] = S[(r0 + i) * 65 + k];
        float4 b = *reinterpret_cast<const float4*>(Ws + k * 64 + c0);
        #pragma unroll
        for (int i = 0; i < 4; ++i) {
            acc[i][0] = fmaf(a[i], b.x, acc[i][0]);
            acc[i][1] = fmaf(a[i], b.y, acc[i][1]);
            acc[i][2] = fmaf(a[i], b.z, acc[i][2]);
            acc[i][3] = fmaf(a[i], b.w, acc[i][3]);
        }
    }

    // out = (1-BETA)*Xi + BETA*(acc + b2)
    #pragma unroll
    for (int i = 0; i < 4; ++i) {
        int row = base + r0 + i;
        if (row < NV) {
            float4 o;
            o.x = (1.f - BETA) * xi[i][0] + BETA * (acc[i][0] + b2r[0]);
            o.y = (1.f - BETA) * xi[i][1] + BETA * (acc[i][1] + b2r[1]);
            o.z = (1.f - BETA) * xi[i][2] + BETA * (acc[i][2] + b2r[2]);
            o.w = (1.f - BETA) * xi[i][3] + BETA * (acc[i][3] + b2r[3]);
            *reinterpret_cast<float4*>(out + (size_t)row * DD + c0) = o;
        }
    }
}

// ---------------------------------------------------------------------------
extern "C" void kernel_launch(void* const* d_in, const int* in_sizes, int n_in,
                              void* d_out, int out_size) {
    const float* X      = (const float*)d_in[0];
    const float* X0     = (const float*)d_in[1];
    const float* W1     = (const float*)d_in[2];
    const float* b1     = (const float*)d_in[3];
    const float* W2     = (const float*)d_in[4];
    const float* b2     = (const float*)d_in[5];
    const int*   vertex = (const int*)d_in[6];
    const int*   edges  = (const int*)d_in[7];
    float*       out    = (float*)d_out;

    const int nnz = in_sizes[6];

    zero_scratch<<<148 * 8, 256>>>();

    long long sthreads = (long long)nnz * 16;
    int sblocks = (int)((sthreads + 255) / 256);
    scatter_v2e<<<sblocks, 256>>>(X, vertex, edges, nnz);
    scatter_e2v<<<sblocks, 256>>>(vertex, edges, nnz);

    int eblocks = (NV + 63) / 64;
    epilogue<<<eblocks, 256>>>(X0, W1, b1, W2, b2, out);
}

// round 3
// speedup vs baseline: 1.0331x; 1.0331x over previous
#include <cuda_runtime.h>
#include <cstdint>

// Problem constants (match reference)
#define NV   100000
#define NE   20000
#define DD   64
#define ALPHA 0.5f
#define BETA  0.5f

#define NBKT (NE + NV)          // combined buckets: [0,NE) edges, [NE,NE+NV) vertices
#define MAXNNZ 1000000

// Scratch (all __device__ globals; no allocation)
__device__ __align__(16) float g_Xe[NE * DD];
__device__ __align__(16) float g_Xv[NV * DD];
__device__ int g_counts[NBKT];
__device__ int g_offs[NBKT];
__device__ int g_cur[NBKT];
__device__ int g_blocksums[128];
__device__ int g_perm[2 * MAXNNZ];   // edge buckets store vertex ids; vertex buckets store edge ids

// ---------------------------------------------------------------------------
// Zero the counts array
// ---------------------------------------------------------------------------
__global__ void zero_counts() {
    int i = blockIdx.x * blockDim.x + threadIdx.x;
    if (i < NBKT) g_counts[i] = 0;
}

// ---------------------------------------------------------------------------
// Histogram: count entries per edge bucket and per vertex bucket
// ---------------------------------------------------------------------------
__global__ void histogram(const int* __restrict__ vertex,
                          const int* __restrict__ edges, int nnz) {
    int i = blockIdx.x * blockDim.x + threadIdx.x;
    if (i >= nnz) return;
    atomicAdd(&g_counts[__ldg(edges + i)], 1);
    atomicAdd(&g_counts[NE + __ldg(vertex + i)], 1);
}

// ---------------------------------------------------------------------------
// Hierarchical exclusive scan of g_counts -> g_offs (3 kernels)
// ---------------------------------------------------------------------------
__global__ __launch_bounds__(1024) void scan1() {
    __shared__ int s[1024];
    int tid = threadIdx.x;
    int i = blockIdx.x * 1024 + tid;
    int v = (i < NBKT) ? g_counts[i] : 0;
    s[tid] = v;
    __syncthreads();
    #pragma unroll
    for (int d = 1; d < 1024; d <<= 1) {
        int t = (tid >= d) ? s[tid - d] : 0;
        __syncthreads();
        s[tid] += t;
        __syncthreads();
    }
    if (i < NBKT) g_offs[i] = s[tid] - v;       // exclusive within block
    if (tid == 1023) g_blocksums[blockIdx.x] = s[tid];
}

__global__ void scan2(int nblocks) {
    __shared__ int s[128];
    int tid = threadIdx.x;
    int v = (tid < nblocks) ? g_blocksums[tid] : 0;
    s[tid] = v;
    __syncthreads();
    #pragma unroll
    for (int d = 1; d < 128; d <<= 1) {
        int t = (tid >= d) ? s[tid - d] : 0;
        __syncthreads();
        s[tid] += t;
        __syncthreads();
    }
    if (tid < nblocks) g_blocksums[tid] = s[tid] - v;  // exclusive block offsets
}

__global__ void scan3() {
    int i = blockIdx.x * blockDim.x + threadIdx.x;
    if (i < NBKT) {
        int o = g_offs[i] + g_blocksums[i >> 10];
        g_offs[i] = o;
        g_cur[i] = o;
    }
}

// ---------------------------------------------------------------------------
// Fill perm: bucket-sort the nnz entries into both CSRs
// ---------------------------------------------------------------------------
__global__ void fill_perm(const int* __restrict__ vertex,
                          const int* __restrict__ edges, int nnz) {
    int i = blockIdx.x * blockDim.x + threadIdx.x;
    if (i >= nnz) return;
    int e = __ldg(edges + i);
    int v = __ldg(vertex + i);
    int p = atomicAdd(&g_cur[e], 1);
    g_perm[p] = v;
    int q = atomicAdd(&g_cur[NE + v], 1);
    g_perm[q] = e;
}

// ---------------------------------------------------------------------------
// Gather phase 1: Xe[e] = sum over vertices in edge bucket of X[v]
// 16 threads per bucket, each owns 4 floats; unroll-4 for MLP.
// ---------------------------------------------------------------------------
__device__ __forceinline__ void f4acc(float4& a, float4 x) {
    a.x += x.x; a.y += x.y; a.z += x.z; a.w += x.w;
}

template <int BASE>
__device__ __forceinline__ float4 gather_bucket(const float* __restrict__ src,
                                                int b, int c) {
    int start = __ldg(g_offs + BASE + b);
    int deg   = __ldg(g_counts + BASE + b);
    float4 a0 = make_float4(0.f, 0.f, 0.f, 0.f);
    float4 a1 = a0, a2 = a0, a3 = a0;
    int j = 0;
    for (; j + 4 <= deg; j += 4) {
        int i0 = __ldg(g_perm + start + j);
        int i1 = __ldg(g_perm + start + j + 1);
        int i2 = __ldg(g_perm + start + j + 2);
        int i3 = __ldg(g_perm + start + j + 3);
        f4acc(a0, *reinterpret_cast<const float4*>(src + (size_t)i0 * DD + c));
        f4acc(a1, *reinterpret_cast<const float4*>(src + (size_t)i1 * DD + c));
        f4acc(a2, *reinterpret_cast<const float4*>(src + (size_t)i2 * DD + c));
        f4acc(a3, *reinterpret_cast<const float4*>(src + (size_t)i3 * DD + c));
    }
    for (; j < deg; ++j) {
        int i0 = __ldg(g_perm + start + j);
        f4acc(a0, *reinterpret_cast<const float4*>(src + (size_t)i0 * DD + c));
    }
    float4 r;
    r.x = (a0.x + a1.x) + (a2.x + a3.x);
    r.y = (a0.y + a1.y) + (a2.y + a3.y);
    r.z = (a0.z + a1.z) + (a2.z + a3.z);
    r.w = (a0.w + a1.w) + (a2.w + a3.w);
    return r;
}

__global__ __launch_bounds__(256) void gather_e(const float* __restrict__ X) {
    int t = blockIdx.x * blockDim.x + threadIdx.x;
    int b = t >> 4;
    if (b >= NE) return;
    int c = (t & 15) << 2;
    float4 r = gather_bucket<0>(X, b, c);
    *reinterpret_cast<float4*>(g_Xe + (size_t)b * DD + c) = r;
}

__global__ __launch_bounds__(256) void gather_v() {
    int t = blockIdx.x * blockDim.x + threadIdx.x;
    int b = t >> 4;
    if (b >= NV) return;
    int c = (t & 15) << 2;
    float4 r = gather_bucket<NE>(g_Xe, b, c);
    *reinterpret_cast<float4*>(g_Xv + (size_t)b * DD + c) = r;
}

// ---------------------------------------------------------------------------
// Epilogue: Xi = 0.5*Xv + 0.5*X0 ; h = relu(Xi@W1 + b1) ;
//           out = 0.5*Xi + 0.5*(h@W2 + b2)
// One block = 64 rows. 256 threads, each computes a 4x4 output block.
// ---------------------------------------------------------------------------
__global__ __launch_bounds__(256) void epilogue(
        const float* __restrict__ X0,
        const float* __restrict__ W1, const float* __restrict__ b1,
        const float* __restrict__ W2, const float* __restrict__ b2,
        float* __restrict__ out) {
    __shared__ float S[64 * 65];
    __shared__ float Ws[64 * 64];
    __shared__ float bs[64];

    const int tid  = threadIdx.x;
    const int tr   = tid >> 4;
    const int tc   = tid & 15;
    const int r0   = tr * 4;
    const int c0   = tc * 4;
    const int base = blockIdx.x * 64;

    #pragma unroll
    for (int idx = tid; idx < 64 * 16; idx += 256)
        reinterpret_cast<float4*>(Ws)[idx] = reinterpret_cast<const float4*>(W1)[idx];
    if (tid < 64) bs[tid] = b1[tid];

    for (int idx = tid; idx < 64 * 16; idx += 256) {
        int r = idx >> 4;
        int q = (idx & 15) << 2;
        int row = base + r;
        float4 xv = make_float4(0.f, 0.f, 0.f, 0.f);
        float4 x0 = xv;
        if (row < NV) {
            xv = *reinterpret_cast<const float4*>(g_Xv + (size_t)row * DD + q);
            x0 = *reinterpret_cast<const float4*>(X0   + (size_t)row * DD + q);
        }
        float* s = S + r * 65 + q;
        s[0] = (1.f - ALPHA) * xv.x + ALPHA * x0.x;
        s[1] = (1.f - ALPHA) * xv.y + ALPHA * x0.y;
        s[2] = (1.f - ALPHA) * xv.z + ALPHA * x0.z;
        s[3] = (1.f - ALPHA) * xv.w + ALPHA * x0.w;
    }
    __syncthreads();

    float acc[4][4] = {};
    #pragma unroll 16
    for (int k = 0; k < 64; ++k) {
        float a[4];
        #pragma unroll
        for (int i = 0; i < 4; ++i) a[i] = S[(r0 + i) * 65 + k];
        float4 b = *reinterpret_cast<const float4*>(Ws + k * 64 + c0);
        #pragma unroll
        for (int i = 0; i < 4; ++i) {
            acc[i][0] = fmaf(a[i], b.x, acc[i][0]);
            acc[i][1] = fmaf(a[i], b.y, acc[i][1]);
            acc[i][2] = fmaf(a[i], b.z, acc[i][2]);
            acc[i][3] = fmaf(a[i], b.w, acc[i][3]);
        }
    }

    float xi[4][4];
    #pragma unroll
    for (int i = 0; i < 4; ++i)
        #pragma unroll
        for (int j = 0; j < 4; ++j)
            xi[i][j] = S[(r0 + i) * 65 + c0 + j];
    __syncthreads();

    #pragma unroll
    for (int i = 0; i < 4; ++i)
        #pragma unroll
        for (int j = 0; j < 4; ++j)
            S[(r0 + i) * 65 + c0 + j] = fmaxf(acc[i][j] + bs[c0 + j], 0.f);

    #pragma unroll
    for (int idx = tid; idx < 64 * 16; idx += 256)
        reinterpret_cast<float4*>(Ws)[idx] = reinterpret_cast<const float4*>(W2)[idx];
    __syncthreads();

    float b2r[4];
    #pragma unroll
    for (int j = 0; j < 4; ++j) b2r[j] = __ldg(b2 + c0 + j);

    #pragma unroll
    for (int i = 0; i < 4; ++i)
        #pragma unroll
        for (int j = 0; j < 4; ++j)
            acc[i][j] = 0.f;
    #pragma unroll 16
    for (int k = 0; k < 64; ++k) {
        float a[4];
        #pragma unroll
        for (int i = 0; i < 4; ++i) a[i] = S[(r0 + i) * 65 + k];
        float4 b = *reinterpret_cast<const float4*>(Ws + k * 64 + c0);
        #pragma unroll
        for (int i = 0; i < 4; ++i) {
            acc[i][0] = fmaf(a[i], b.x, acc[i][0]);
            acc[i][1] = fmaf(a[i], b.y, acc[i][1]);
            acc[i][2] = fmaf(a[i], b.z, acc[i][2]);
            acc[i][3] = fmaf(a[i], b.w, acc[i][3]);
        }
    }

    #pragma unroll
    for (int i = 0; i < 4; ++i) {
        int row = base + r0 + i;
        if (row < NV) {
            float4 o;
            o.x = (1.f - BETA) * xi[i][0] + BETA * (acc[i][0] + b2r[0]);
            o.y = (1.f - BETA) * xi[i][1] + BETA * (acc[i][1] + b2r[1]);
            o.z = (1.f - BETA) * xi[i][2] + BETA * (acc[i][2] + b2r[2]);
            o.w = (1.f - BETA) * xi[i][3] + BETA * (acc[i][3] + b2r[3]);
            *reinterpret_cast<float4*>(out + (size_t)row * DD + c0) = o;
        }
    }
}

// ---------------------------------------------------------------------------
extern "C" void kernel_launch(void* const* d_in, const int* in_sizes, int n_in,
                              void* d_out, int out_size) {
    const float* X      = (const float*)d_in[0];
    const float* X0     = (const float*)d_in[1];
    const float* W1     = (const float*)d_in[2];
    const float* b1     = (const float*)d_in[3];
    const float* W2     = (const float*)d_in[4];
    const float* b2     = (const float*)d_in[5];
    const int*   vertex = (const int*)d_in[6];
    const int*   edges  = (const int*)d_in[7];
    float*       out    = (float*)d_out;

    const int nnz = in_sizes[6];
    const int nscan_blocks = (NBKT + 1023) / 1024;

    zero_counts<<<(NBKT + 255) / 256, 256>>>();
    histogram<<<(nnz + 255) / 256, 256>>>(vertex, edges, nnz);
    scan1<<<nscan_blocks, 1024>>>();
    scan2<<<1, 128>>>(nscan_blocks);
    scan3<<<(NBKT + 255) / 256, 256>>>();
    fill_perm<<<(nnz + 255) / 256, 256>>>(vertex, edges, nnz);

    gather_e<<<(NE * 16 + 255) / 256, 256>>>(X);
    gather_v<<<(NV * 16 + 255) / 256, 256>>>();

    epilogue<<<(NV + 63) / 64, 256>>>(X0, W1, b1, W2, b2, out);
}